// round 1
// baseline (speedup 1.0000x reference)
#include <cuda_runtime.h>
#include <math.h>

// Problem constants
#define BB 4
#define SS 2048
#define HH 16
#define DH 64
#define DD 1024            // H*DH
#define ROWS (BB*SS)       // 8192
#define N_QKV (3*DD)       // 3072
#define FF_IN 4096
#define FF_HID 2048

// Scratch (device globals; no allocation)
__device__ float g_qkv [ROWS * N_QKV];   // [B*S, 3072]
__device__ float g_q   [ROWS * DD];      // [B*H, S, 64]
__device__ float g_k   [ROWS * DD];
__device__ float g_v   [ROWS * DD];
__device__ float g_attn[ROWS * DD];      // [B*S, 1024]
__device__ float g_ln  [ROWS * DD];      // [B*S, 1024]
__device__ float g_h   [ROWS * FF_IN];   // [B*S, 4096]
__device__ float g_gate[ROWS * FF_HID];  // [B*S, 2048]

// ---------------------------------------------------------------------------
// Classic 128x128x8 SGEMM, 256 threads, 8x8 microtile. C = A@B + bias (+ res)
// A: [M,K] row-major, B: [K,N] row-major. M,N,K divisible by tile dims.
// ---------------------------------------------------------------------------
#define BM 128
#define BN 128
#define BK 8
#define TM 8
#define TN 8

__global__ __launch_bounds__(256) void sgemm_kernel(
    int M, int N, int K,
    const float* __restrict__ A, const float* __restrict__ B,
    const float* __restrict__ bias, const float* __restrict__ res,
    float* __restrict__ C)
{
    __shared__ float As[BK][BM];
    __shared__ float Bs[BK][BN];

    const int cRow = blockIdx.y;
    const int cCol = blockIdx.x;
    const int tid  = threadIdx.x;

    A += (size_t)cRow * BM * K;
    B += (size_t)cCol * BN;
    C += (size_t)cRow * BM * N + (size_t)cCol * BN;
    if (res) res += (size_t)cRow * BM * N + (size_t)cCol * BN;
    bias += (size_t)cCol * BN;

    const int aRow = tid >> 1;          // 0..127
    const int aCol = (tid & 1) * 4;     // 0 or 4
    const int bRow = tid >> 5;          // 0..7
    const int bCol = (tid & 31) * 4;    // 0..124
    const int tRow = (tid >> 4) * TM;   // 0..120
    const int tCol = (tid & 15) * TN;   // 0..120

    float acc[TM][TN] = {};
    float regA[TM], regB[TN];

    for (int k0 = 0; k0 < K; k0 += BK) {
        float4 a = *(const float4*)(A + (size_t)aRow * K + k0 + aCol);
        As[aCol + 0][aRow] = a.x;
        As[aCol + 1][aRow] = a.y;
        As[aCol + 2][aRow] = a.z;
        As[aCol + 3][aRow] = a.w;
        *(float4*)(&Bs[bRow][bCol]) = *(const float4*)(B + (size_t)(k0 + bRow) * N + bCol);
        __syncthreads();

#pragma unroll
        for (int k = 0; k < BK; k++) {
#pragma unroll
            for (int i = 0; i < TM; i++) regA[i] = As[k][tRow + i];
#pragma unroll
            for (int j = 0; j < TN; j++) regB[j] = Bs[k][tCol + j];
#pragma unroll
            for (int i = 0; i < TM; i++)
#pragma unroll
                for (int j = 0; j < TN; j++)
                    acc[i][j] += regA[i] * regB[j];
        }
        __syncthreads();
    }

#pragma unroll
    for (int i = 0; i < TM; i++) {
        const int r = tRow + i;
#pragma unroll
        for (int j = 0; j < TN; j += 4) {
            float4 o;
            o.x = acc[i][j + 0] + bias[tCol + j + 0];
            o.y = acc[i][j + 1] + bias[tCol + j + 1];
            o.z = acc[i][j + 2] + bias[tCol + j + 2];
            o.w = acc[i][j + 3] + bias[tCol + j + 3];
            if (res) {
                float4 rv = *(const float4*)(res + (size_t)r * N + tCol + j);
                o.x += rv.x; o.y += rv.y; o.z += rv.z; o.w += rv.w;
            }
            *(float4*)(C + (size_t)r * N + tCol + j) = o;
        }
    }
}

// ---------------------------------------------------------------------------
// l2norm + scale + xpos-RoPE, and scatter q/k/v to [B*H, S, 64] layout.
// One warp per (b, s, h). Lane handles dims {lane, lane+32}.
// ---------------------------------------------------------------------------
__global__ __launch_bounds__(256) void normrope_kernel(
    const float* __restrict__ q_scale, const float* __restrict__ k_scale)
{
    const int w    = blockIdx.x * 8 + (threadIdx.x >> 5);   // warp id, 0..131071
    const int lane = threadIdx.x & 31;

    const int h    = w & 15;
    const int spos = (w >> 4) & (SS - 1);
    const int b    = w >> 15;                                // / (16*2048)
    const int bs   = (b * SS + spos);

    const float* base = g_qkv + (size_t)bs * N_QKV + h * 192;

    float q0 = base[lane],       q1 = base[lane + 32];
    float k0 = base[64 + lane],  k1 = base[96 + lane];
    float v0 = base[128 + lane], v1 = base[160 + lane];

    float sq = q0 * q0 + q1 * q1;
    float sk = k0 * k0 + k1 * k1;
#pragma unroll
    for (int o = 16; o > 0; o >>= 1) {
        sq += __shfl_xor_sync(0xffffffffu, sq, o);
        sk += __shfl_xor_sync(0xffffffffu, sk, o);
    }
    const float invq = 1.0f / fmaxf(sqrtf(sq), 1e-12f);
    const float invk = 1.0f / fmaxf(sqrtf(sk), 1e-12f);

    q0 = q0 * invq * q_scale[lane];
    q1 = q1 * invq * q_scale[lane + 32];
    k0 = k0 * invk * k_scale[lane];
    k1 = k1 * invk * k_scale[lane + 32];

    // rotary tables (j = lane for both halves)
    const float inv_freq = expf(-((2.0f * lane) / 64.0f) * 9.210340371976184f); // ln(10000)
    const float f = (float)spos * inv_freq;
    float sn, cs;
    sincosf(f, &sn, &cs);
    const float power = ((float)spos - 1024.0f) * (1.0f / 512.0f);
    const float bse   = (2.0f * lane + 25.6f) * (1.0f / 89.6f);
    const float sc    = powf(bse, power);
    const float sci   = 1.0f / sc;

    // rotate_half: d<32 -> -t[d+32]; d>=32 -> t[d-32]
    const float q0r = (q0 * cs - q1 * sn) * sc;
    const float q1r = (q1 * cs + q0 * sn) * sc;
    const float k0r = (k0 * cs - k1 * sn) * sci;
    const float k1r = (k1 * cs + k0 * sn) * sci;

    const int bh = b * HH + h;
    const size_t o = ((size_t)bh * SS + spos) * DH;
    g_q[o + lane] = q0r;  g_q[o + lane + 32] = q1r;
    g_k[o + lane] = k0r;  g_k[o + lane + 32] = k1r;
    g_v[o + lane] = v0;   g_v[o + lane + 32] = v1;
}

// ---------------------------------------------------------------------------
// Flash attention (non-causal), fp32. One q-row per thread, 128 rows/block.
// KV tiles of 64 staged in shared memory. Online softmax per thread.
// Writes to g_attn in [B*S, 1024] layout (head-interleaved).
// ---------------------------------------------------------------------------
__global__ __launch_bounds__(128) void attn_kernel()
{
    const int bh   = blockIdx.x;               // 0..63
    const int tid  = threadIdx.x;              // 0..127
    const int row  = blockIdx.y * 128 + tid;   // q row in [0,2048)

    const float* Q = g_q + (size_t)bh * SS * DH;
    const float* K = g_k + (size_t)bh * SS * DH;
    const float* V = g_v + (size_t)bh * SS * DH;

    __shared__ float Ks[64][DH];
    __shared__ float Vs[64][DH];

    float q[DH];
#pragma unroll
    for (int d4 = 0; d4 < 16; d4++)
        *(float4*)(q + 4 * d4) = ((const float4*)(Q + (size_t)row * DH))[d4];

    float acc[DH] = {};
    float m = -1e30f, l = 0.0f;

    for (int kb = 0; kb < SS; kb += 64) {
        __syncthreads();
        const float4* Kg = (const float4*)(K + (size_t)kb * DH);
        const float4* Vg = (const float4*)(V + (size_t)kb * DH);
        float4* Ks4 = (float4*)&Ks[0][0];
        float4* Vs4 = (float4*)&Vs[0][0];
#pragma unroll
        for (int i = 0; i < 8; i++) {
            Ks4[tid + 128 * i] = Kg[tid + 128 * i];
            Vs4[tid + 128 * i] = Vg[tid + 128 * i];
        }
        __syncthreads();

        for (int j = 0; j < 64; j++) {
            float s = 0.0f;
            const float4* kr = (const float4*)Ks[j];
#pragma unroll
            for (int d4 = 0; d4 < 16; d4++) {
                float4 kk = kr[d4];
                s += q[4*d4+0]*kk.x + q[4*d4+1]*kk.y + q[4*d4+2]*kk.z + q[4*d4+3]*kk.w;
            }
            s *= 0.125f;
            const float4* vr = (const float4*)Vs[j];
            if (s > m) {
                const float corr = __expf(m - s);
                m = s;
                l = l * corr + 1.0f;
#pragma unroll
                for (int d4 = 0; d4 < 16; d4++) {
                    float4 vv = vr[d4];
                    acc[4*d4+0] = acc[4*d4+0]*corr + vv.x;
                    acc[4*d4+1] = acc[4*d4+1]*corr + vv.y;
                    acc[4*d4+2] = acc[4*d4+2]*corr + vv.z;
                    acc[4*d4+3] = acc[4*d4+3]*corr + vv.w;
                }
            } else {
                const float p = __expf(s - m);
                l += p;
#pragma unroll
                for (int d4 = 0; d4 < 16; d4++) {
                    float4 vv = vr[d4];
                    acc[4*d4+0] += p * vv.x;
                    acc[4*d4+1] += p * vv.y;
                    acc[4*d4+2] += p * vv.z;
                    acc[4*d4+3] += p * vv.w;
                }
            }
        }
    }

    const float inv = 1.0f / l;
    const int b = bh >> 4, h = bh & 15;
    float* out = g_attn + ((size_t)(b * SS + row)) * DD + h * DH;
#pragma unroll
    for (int d4 = 0; d4 < 16; d4++) {
        float4 o;
        o.x = acc[4*d4+0]*inv; o.y = acc[4*d4+1]*inv;
        o.z = acc[4*d4+2]*inv; o.w = acc[4*d4+3]*inv;
        ((float4*)out)[d4] = o;
    }
}

// ---------------------------------------------------------------------------
// LayerNorm over 1024 dims; one block (256 threads) per row.
// ---------------------------------------------------------------------------
__global__ __launch_bounds__(256) void ln_kernel(
    const float* __restrict__ gw, const float* __restrict__ bw)
{
    __shared__ float red[64];
    const int r = blockIdx.x;
    const int t = threadIdx.x;

    const float4 x = ((const float4*)(g_attn + (size_t)r * DD))[t];
    float s  = x.x + x.y + x.z + x.w;
    float ss = x.x*x.x + x.y*x.y + x.z*x.z + x.w*x.w;
#pragma unroll
    for (int o = 16; o > 0; o >>= 1) {
        s  += __shfl_xor_sync(0xffffffffu, s,  o);
        ss += __shfl_xor_sync(0xffffffffu, ss, o);
    }
    if ((t & 31) == 0) { red[t >> 5] = s; red[32 + (t >> 5)] = ss; }
    __syncthreads();
    if (t == 0) {
        float S = 0, SSum = 0;
#pragma unroll
        for (int i = 0; i < 8; i++) { S += red[i]; SSum += red[32 + i]; }
        red[0] = S; red[32] = SSum;
    }
    __syncthreads();
    const float mu  = red[0]  * (1.0f / DD);
    const float var = red[32] * (1.0f / DD) - mu * mu;
    const float inv = rsqrtf(var + 1e-5f);

    const int c = t * 4;
    float4 o;
    o.x = (x.x - mu) * inv * gw[c + 0] + bw[c + 0];
    o.y = (x.y - mu) * inv * gw[c + 1] + bw[c + 1];
    o.z = (x.z - mu) * inv * gw[c + 2] + bw[c + 2];
    o.w = (x.w - mu) * inv * gw[c + 3] + bw[c + 3];
    ((float4*)(g_ln + (size_t)r * DD))[t] = o;
}

// ---------------------------------------------------------------------------
// SwiGLU: g = x * silu(gate), x = h[:, :2048], gate = h[:, 2048:]
// ---------------------------------------------------------------------------
__global__ __launch_bounds__(256) void swiglu_kernel()
{
    const int idx4 = blockIdx.x * 256 + threadIdx.x;   // float4 index into [8192,2048]
    const int r    = idx4 >> 9;                        // /512
    const int c4   = idx4 & 511;
    const float4 xv = ((const float4*)(g_h + (size_t)r * FF_IN))[c4];
    const float4 gv = ((const float4*)(g_h + (size_t)r * FF_IN + FF_HID))[c4];
    float4 o;
    o.x = xv.x * gv.x / (1.0f + __expf(-gv.x));
    o.y = xv.y * gv.y / (1.0f + __expf(-gv.y));
    o.z = xv.z * gv.z / (1.0f + __expf(-gv.z));
    o.w = xv.w * gv.w / (1.0f + __expf(-gv.w));
    ((float4*)(g_gate + (size_t)r * FF_HID))[c4] = o;
}

// ---------------------------------------------------------------------------
extern "C" void kernel_launch(void* const* d_in, const int* in_sizes, int n_in,
                              void* d_out, int out_size)
{
    const float* q       = (const float*)d_in[0];
    // d_in[1] (k), d_in[2] (v) unused per reference semantics
    const float* Wqkv    = (const float*)d_in[3];
    const float* bqkv    = (const float*)d_in[4];
    const float* q_scale = (const float*)d_in[5];
    const float* k_scale = (const float*)d_in[6];
    const float* ln_g    = (const float*)d_in[7];
    const float* ln_b    = (const float*)d_in[8];
    const float* W1      = (const float*)d_in[9];
    const float* b1      = (const float*)d_in[10];
    const float* W2      = (const float*)d_in[11];
    const float* b2      = (const float*)d_in[12];
    float* out = (float*)d_out;

    float *p_qkv, *p_ln, *p_h, *p_gate;
    cudaGetSymbolAddress((void**)&p_qkv,  g_qkv);
    cudaGetSymbolAddress((void**)&p_ln,   g_ln);
    cudaGetSymbolAddress((void**)&p_h,    g_h);
    cudaGetSymbolAddress((void**)&p_gate, g_gate);

    // 1) QKV projection: [8192,1024] @ [1024,3072] + bqkv
    sgemm_kernel<<<dim3(N_QKV / BN, ROWS / BM), 256>>>(
        ROWS, N_QKV, DD, q, Wqkv, bqkv, nullptr, p_qkv);

    // 2) l2norm + scale + RoPE, scatter to [B*H,S,64]
    normrope_kernel<<<(BB * SS * HH) / 8, 256>>>(q_scale, k_scale);

    // 3) attention
    attn_kernel<<<dim3(BB * HH, SS / 128), 128>>>();

    // 4) LayerNorm
    ln_kernel<<<ROWS, 256>>>(ln_g, ln_b);

    // 5) FF1: [8192,1024] @ [1024,4096] + b1
    sgemm_kernel<<<dim3(FF_IN / BN, ROWS / BM), 256>>>(
        ROWS, FF_IN, DD, p_ln, W1, b1, nullptr, p_h);

    // 6) SwiGLU
    swiglu_kernel<<<(ROWS * FF_HID / 4) / 256, 256>>>();

    // 7) FF2 + bias + residual(ln): [8192,2048] @ [2048,1024] + b2 + ln
    sgemm_kernel<<<dim3(DD / BN, ROWS / BM), 256>>>(
        ROWS, DD, FF_HID, p_gate, W2, b2, p_ln, out);
}

// round 4
// speedup vs baseline: 1.6919x; 1.6919x over previous
#include <cuda_runtime.h>
#include <math.h>
#include <stdint.h>

// Problem constants
#define BB 4
#define SS 2048
#define HH 16
#define DH 64
#define DD 1024            // H*DH
#define ROWS (BB*SS)       // 8192
#define N_QKV (3*DD)       // 3072
#define FF_IN 4096
#define FF_HID 2048

// Scratch (device globals; no allocation)
__device__ float g_qkv [(size_t)ROWS * N_QKV];   // [B*S, 3072]
__device__ float g_aq  [(size_t)ROWS * DD];      // tf32-rounded q
__device__ float g_q   [(size_t)ROWS * DD];      // [B*H, S, 64]
__device__ float g_k   [(size_t)ROWS * DD];
__device__ float g_v   [(size_t)ROWS * DD];
__device__ float g_attn[(size_t)ROWS * DD];      // [B*S, 1024]
__device__ float g_ln  [(size_t)ROWS * DD];      // LN out (fp32, residual)
__device__ float g_lnr [(size_t)ROWS * DD];      // LN out tf32-rounded (GEMM A)
__device__ float g_h   [(size_t)ROWS * FF_IN];   // [B*S, 4096]
__device__ float g_gate[(size_t)ROWS * FF_HID];  // [B*S, 2048] tf32-rounded
__device__ float g_wqkvT[(size_t)N_QKV * DD];    // [3072, 1024]
__device__ float g_w1T  [(size_t)FF_IN * DD];    // [4096, 1024]
__device__ float g_w2T  [(size_t)DD * FF_HID];   // [1024, 2048]

// ---------------------------------------------------------------------------
// helpers
// ---------------------------------------------------------------------------
__device__ __forceinline__ float tf32r(float x) {
    float o; asm("cvt.rna.tf32.f32 %0, %1;" : "=f"(o) : "f"(x)); return o;
}
__device__ __forceinline__ uint32_t smem_u32(const void* p) {
    uint32_t a;
    asm("{ .reg .u64 t; cvta.to.shared.u64 t, %1; cvt.u32.u64 %0, t; }" : "=r"(a) : "l"(p));
    return a;
}
__device__ __forceinline__ void cpasync16(uint32_t dst, const void* src) {
    asm volatile("cp.async.cg.shared.global [%0], [%1], 16;" :: "r"(dst), "l"(src) : "memory");
}
__device__ __forceinline__ void cp_commit() {
    asm volatile("cp.async.commit_group;" ::: "memory");
}
__device__ __forceinline__ void cp_wait1() {
    asm volatile("cp.async.wait_group 1;" ::: "memory");
}
__device__ __forceinline__ void cp_wait0() {
    asm volatile("cp.async.wait_group 0;" ::: "memory");
}
__device__ __forceinline__ void mma_tf32(float* c, const uint32_t* a, const uint32_t* b) {
    asm volatile(
        "mma.sync.aligned.m16n8k8.row.col.f32.tf32.tf32.f32 "
        "{%0,%1,%2,%3}, {%4,%5,%6,%7}, {%8,%9}, {%0,%1,%2,%3};"
        : "+f"(c[0]), "+f"(c[1]), "+f"(c[2]), "+f"(c[3])
        : "r"(a[0]), "r"(a[1]), "r"(a[2]), "r"(a[3]), "r"(b[0]), "r"(b[1]));
}

// ---------------------------------------------------------------------------
// tf32 mma.sync GEMM: C[M,N] = A[M,K] @ Bt[N,K]^T + bias (+ res)
// A row-major [M,K] (tf32-rounded); Bt row-major [N,K] (transposed weights).
// CTA tile 128x128, BK=32, 256 threads (8 warps, 4m x 2n, warp tile 32x64).
// Double-buffered cp.async. Smem row pad 36 floats -> conflict-free frags.
// ---------------------------------------------------------------------------
#define GBM 128
#define GBN 128
#define GBK 32
#define APAD 36
#define STAGE_F (2 * 128 * APAD)   // floats per stage (A+B)

__global__ __launch_bounds__(256) void gemm_mma_kernel(
    const float* __restrict__ A, const float* __restrict__ Bt,
    const float* __restrict__ bias, const float* __restrict__ res,
    float* __restrict__ C, int N, int K)
{
    extern __shared__ float sm[];
    const int tid = threadIdx.x;
    const int wid = tid >> 5, lane = tid & 31;
    const int g = lane >> 2, tg = lane & 3;
    const int warp_m = wid & 3, warp_n = wid >> 2;
    const int m0 = blockIdx.y * GBM, n0 = blockIdx.x * GBN;
    const uint32_t smbase = smem_u32(sm);

    float acc[2][8][4] = {};

    const int NIT = K >> 5;

    // stage loader: 8 cp.async16 per thread
    auto load_stage = [&](int it, int s) {
        const int k0 = it * GBK;
        const uint32_t aB = smbase + (uint32_t)s * STAGE_F * 4;
        const uint32_t bB = aB + 128 * APAD * 4;
#pragma unroll
        for (int i = 0; i < 4; i++) {
            const int idx = tid + 256 * i;
            const int row = idx >> 3, c4 = (idx & 7) * 4;
            cpasync16(aB + (uint32_t)(row * APAD + c4) * 4,
                      A  + (size_t)(m0 + row) * K + k0 + c4);
            cpasync16(bB + (uint32_t)(row * APAD + c4) * 4,
                      Bt + (size_t)(n0 + row) * K + k0 + c4);
        }
        cp_commit();
    };

    load_stage(0, 0);

    for (int it = 0; it < NIT; it++) {
        const int s = it & 1;
        if (it + 1 < NIT) load_stage(it + 1, s ^ 1);
        if (it + 1 < NIT) cp_wait1(); else cp_wait0();
        __syncthreads();

        const uint32_t* Asm = (const uint32_t*)(sm + s * STAGE_F);
        const uint32_t* Bsm = Asm + 128 * APAD;

#pragma unroll
        for (int kt = 0; kt < 4; kt++) {
            const int k = kt * 8;
            uint32_t a[2][4], b[8][2];
#pragma unroll
            for (int mi = 0; mi < 2; mi++) {
                const uint32_t* ap = Asm + (warp_m * 32 + mi * 16 + g) * APAD + k + tg;
                a[mi][0] = ap[0];
                a[mi][1] = ap[8 * APAD];
                a[mi][2] = ap[4];
                a[mi][3] = ap[8 * APAD + 4];
            }
#pragma unroll
            for (int ni = 0; ni < 8; ni++) {
                const uint32_t* bp = Bsm + (warp_n * 64 + ni * 8 + g) * APAD + k + tg;
                b[ni][0] = bp[0];
                b[ni][1] = bp[4];
            }
#pragma unroll
            for (int mi = 0; mi < 2; mi++)
#pragma unroll
                for (int ni = 0; ni < 8; ni++)
                    mma_tf32(acc[mi][ni], a[mi], b[ni]);
        }
        __syncthreads();
    }

    // epilogue
#pragma unroll
    for (int mi = 0; mi < 2; mi++) {
        const int row0 = m0 + warp_m * 32 + mi * 16 + g;
#pragma unroll
        for (int ni = 0; ni < 8; ni++) {
            const int col = n0 + warp_n * 64 + ni * 8 + tg * 2;
            const float2 bv = *(const float2*)(bias + col);
            float2 o0, o1;
            o0.x = acc[mi][ni][0] + bv.x;
            o0.y = acc[mi][ni][1] + bv.y;
            o1.x = acc[mi][ni][2] + bv.x;
            o1.y = acc[mi][ni][3] + bv.y;
            if (res) {
                const float2 r0 = *(const float2*)(res + (size_t)row0 * N + col);
                const float2 r1 = *(const float2*)(res + (size_t)(row0 + 8) * N + col);
                o0.x += r0.x; o0.y += r0.y; o1.x += r1.x; o1.y += r1.y;
            }
            *(float2*)(C + (size_t)row0 * N + col) = o0;
            *(float2*)(C + (size_t)(row0 + 8) * N + col) = o1;
        }
    }
}

// ---------------------------------------------------------------------------
// Transpose + tf32-round: out[c*R + r] = rnd(in[r*Cc + c])
// ---------------------------------------------------------------------------
__global__ __launch_bounds__(256) void transpose_round_kernel(
    const float* __restrict__ in, float* __restrict__ out, int R, int Cc)
{
    __shared__ float t[32][33];
    const int bx = blockIdx.x, by = blockIdx.y;
    const int tx = threadIdx.x, ty = threadIdx.y;
#pragma unroll
    for (int i = 0; i < 32; i += 8)
        t[ty + i][tx] = in[(size_t)(by * 32 + ty + i) * Cc + bx * 32 + tx];
    __syncthreads();
#pragma unroll
    for (int i = 0; i < 32; i += 8)
        out[(size_t)(bx * 32 + ty + i) * R + by * 32 + tx] = tf32r(t[tx][ty + i]);
}

__global__ __launch_bounds__(256) void round_copy_kernel(
    const float* __restrict__ in, float* __restrict__ out)
{
    const int i = blockIdx.x * 256 + threadIdx.x;
    float4 v = ((const float4*)in)[i];
    v.x = tf32r(v.x); v.y = tf32r(v.y); v.z = tf32r(v.z); v.w = tf32r(v.w);
    ((float4*)out)[i] = v;
}

// ---------------------------------------------------------------------------
// l2norm + scale + xpos-RoPE, scatter q/k/v to [B*H, S, 64]
// ---------------------------------------------------------------------------
__global__ __launch_bounds__(256) void normrope_kernel(
    const float* __restrict__ q_scale, const float* __restrict__ k_scale)
{
    const int w    = blockIdx.x * 8 + (threadIdx.x >> 5);
    const int lane = threadIdx.x & 31;

    const int h    = w & 15;
    const int spos = (w >> 4) & (SS - 1);
    const int b    = w >> 15;
    const int bs   = (b * SS + spos);

    const float* base = g_qkv + (size_t)bs * N_QKV + h * 192;

    float q0 = base[lane],       q1 = base[lane + 32];
    float k0 = base[64 + lane],  k1 = base[96 + lane];
    float v0 = base[128 + lane], v1 = base[160 + lane];

    float sq = q0 * q0 + q1 * q1;
    float sk = k0 * k0 + k1 * k1;
#pragma unroll
    for (int o = 16; o > 0; o >>= 1) {
        sq += __shfl_xor_sync(0xffffffffu, sq, o);
        sk += __shfl_xor_sync(0xffffffffu, sk, o);
    }
    const float invq = 1.0f / fmaxf(sqrtf(sq), 1e-12f);
    const float invk = 1.0f / fmaxf(sqrtf(sk), 1e-12f);

    q0 = q0 * invq * q_scale[lane];
    q1 = q1 * invq * q_scale[lane + 32];
    k0 = k0 * invk * k_scale[lane];
    k1 = k1 * invk * k_scale[lane + 32];

    const float inv_freq = expf(-((2.0f * lane) / 64.0f) * 9.210340371976184f);
    const float f = (float)spos * inv_freq;
    float sn, cs;
    sincosf(f, &sn, &cs);
    const float power = ((float)spos - 1024.0f) * (1.0f / 512.0f);
    const float bse   = (2.0f * lane + 25.6f) * (1.0f / 89.6f);
    const float sc    = powf(bse, power);
    const float sci   = 1.0f / sc;

    const float q0r = (q0 * cs - q1 * sn) * sc;
    const float q1r = (q1 * cs + q0 * sn) * sc;
    const float k0r = (k0 * cs - k1 * sn) * sci;
    const float k1r = (k1 * cs + k0 * sn) * sci;

    const int bh = b * HH + h;
    const size_t o = ((size_t)bh * SS + spos) * DH;
    g_q[o + lane] = q0r;  g_q[o + lane + 32] = q1r;
    g_k[o + lane] = k0r;  g_k[o + lane + 32] = k1r;
    g_v[o + lane] = v0;   g_v[o + lane + 32] = v1;
}

// ---------------------------------------------------------------------------
// Flash attention (non-causal), fp32. One q-row per thread.
// ---------------------------------------------------------------------------
__global__ __launch_bounds__(128) void attn_kernel()
{
    const int bh   = blockIdx.x;
    const int tid  = threadIdx.x;
    const int row  = blockIdx.y * 128 + tid;

    const float* Q = g_q + (size_t)bh * SS * DH;
    const float* K = g_k + (size_t)bh * SS * DH;
    const float* V = g_v + (size_t)bh * SS * DH;

    __shared__ float Ks[64][DH];
    __shared__ float Vs[64][DH];

    float q[DH];
#pragma unroll
    for (int d4 = 0; d4 < 16; d4++)
        *(float4*)(q + 4 * d4) = ((const float4*)(Q + (size_t)row * DH))[d4];

    float acc[DH] = {};
    float m = -1e30f, l = 0.0f;

    for (int kb = 0; kb < SS; kb += 64) {
        __syncthreads();
        const float4* Kg = (const float4*)(K + (size_t)kb * DH);
        const float4* Vg = (const float4*)(V + (size_t)kb * DH);
        float4* Ks4 = (float4*)&Ks[0][0];
        float4* Vs4 = (float4*)&Vs[0][0];
#pragma unroll
        for (int i = 0; i < 8; i++) {
            Ks4[tid + 128 * i] = Kg[tid + 128 * i];
            Vs4[tid + 128 * i] = Vg[tid + 128 * i];
        }
        __syncthreads();

        for (int j = 0; j < 64; j++) {
            float s = 0.0f;
            const float4* kr = (const float4*)Ks[j];
#pragma unroll
            for (int d4 = 0; d4 < 16; d4++) {
                float4 kk = kr[d4];
                s += q[4*d4+0]*kk.x + q[4*d4+1]*kk.y + q[4*d4+2]*kk.z + q[4*d4+3]*kk.w;
            }
            s *= 0.125f;
            const float4* vr = (const float4*)Vs[j];
            if (s > m) {
                const float corr = __expf(m - s);
                m = s;
                l = l * corr + 1.0f;
#pragma unroll
                for (int d4 = 0; d4 < 16; d4++) {
                    float4 vv = vr[d4];
                    acc[4*d4+0] = acc[4*d4+0]*corr + vv.x;
                    acc[4*d4+1] = acc[4*d4+1]*corr + vv.y;
                    acc[4*d4+2] = acc[4*d4+2]*corr + vv.z;
                    acc[4*d4+3] = acc[4*d4+3]*corr + vv.w;
                }
            } else {
                const float p = __expf(s - m);
                l += p;
#pragma unroll
                for (int d4 = 0; d4 < 16; d4++) {
                    float4 vv = vr[d4];
                    acc[4*d4+0] += p * vv.x;
                    acc[4*d4+1] += p * vv.y;
                    acc[4*d4+2] += p * vv.z;
                    acc[4*d4+3] += p * vv.w;
                }
            }
        }
    }

    const float inv = 1.0f / l;
    const int b = bh >> 4, h = bh & 15;
    float* out = g_attn + ((size_t)(b * SS + row)) * DD + h * DH;
#pragma unroll
    for (int d4 = 0; d4 < 16; d4++) {
        float4 o;
        o.x = acc[4*d4+0]*inv; o.y = acc[4*d4+1]*inv;
        o.z = acc[4*d4+2]*inv; o.w = acc[4*d4+3]*inv;
        ((float4*)out)[d4] = o;
    }
}

// ---------------------------------------------------------------------------
// LayerNorm; writes fp32 g_ln (residual) and tf32-rounded g_lnr (GEMM A)
// ---------------------------------------------------------------------------
__global__ __launch_bounds__(256) void ln_kernel(
    const float* __restrict__ gw, const float* __restrict__ bw)
{
    __shared__ float red[64];
    const int r = blockIdx.x;
    const int t = threadIdx.x;

    const float4 x = ((const float4*)(g_attn + (size_t)r * DD))[t];
    float s  = x.x + x.y + x.z + x.w;
    float ss = x.x*x.x + x.y*x.y + x.z*x.z + x.w*x.w;
#pragma unroll
    for (int o = 16; o > 0; o >>= 1) {
        s  += __shfl_xor_sync(0xffffffffu, s,  o);
        ss += __shfl_xor_sync(0xffffffffu, ss, o);
    }
    if ((t & 31) == 0) { red[t >> 5] = s; red[32 + (t >> 5)] = ss; }
    __syncthreads();
    if (t == 0) {
        float S = 0, SSum = 0;
#pragma unroll
        for (int i = 0; i < 8; i++) { S += red[i]; SSum += red[32 + i]; }
        red[0] = S; red[32] = SSum;
    }
    __syncthreads();
    const float mu  = red[0]  * (1.0f / DD);
    const float var = red[32] * (1.0f / DD) - mu * mu;
    const float inv = rsqrtf(var + 1e-5f);

    const int c = t * 4;
    float4 o;
    o.x = (x.x - mu) * inv * gw[c + 0] + bw[c + 0];
    o.y = (x.y - mu) * inv * gw[c + 1] + bw[c + 1];
    o.z = (x.z - mu) * inv * gw[c + 2] + bw[c + 2];
    o.w = (x.w - mu) * inv * gw[c + 3] + bw[c + 3];
    ((float4*)(g_ln + (size_t)r * DD))[t] = o;
    float4 orr;
    orr.x = tf32r(o.x); orr.y = tf32r(o.y); orr.z = tf32r(o.z); orr.w = tf32r(o.w);
    ((float4*)(g_lnr + (size_t)r * DD))[t] = orr;
}

// ---------------------------------------------------------------------------
// SwiGLU (tf32-rounded output for FF2 A operand)
// ---------------------------------------------------------------------------
__global__ __launch_bounds__(256) void swiglu_kernel()
{
    const int idx4 = blockIdx.x * 256 + threadIdx.x;
    const int r    = idx4 >> 9;
    const int c4   = idx4 & 511;
    const float4 xv = ((const float4*)(g_h + (size_t)r * FF_IN))[c4];
    const float4 gv = ((const float4*)(g_h + (size_t)r * FF_IN + FF_HID))[c4];
    float4 o;
    o.x = tf32r(xv.x * gv.x / (1.0f + __expf(-gv.x)));
    o.y = tf32r(xv.y * gv.y / (1.0f + __expf(-gv.y)));
    o.z = tf32r(xv.z * gv.z / (1.0f + __expf(-gv.z)));
    o.w = tf32r(xv.w * gv.w / (1.0f + __expf(-gv.w)));
    ((float4*)(g_gate + (size_t)r * FF_HID))[c4] = o;
}

// ---------------------------------------------------------------------------
extern "C" void kernel_launch(void* const* d_in, const int* in_sizes, int n_in,
                              void* d_out, int out_size)
{
    const float* q       = (const float*)d_in[0];
    const float* Wqkv    = (const float*)d_in[3];
    const float* bqkv    = (const float*)d_in[4];
    const float* q_scale = (const float*)d_in[5];
    const float* k_scale = (const float*)d_in[6];
    const float* ln_g    = (const float*)d_in[7];
    const float* ln_b    = (const float*)d_in[8];
    const float* W1      = (const float*)d_in[9];
    const float* b1      = (const float*)d_in[10];
    const float* W2      = (const float*)d_in[11];
    const float* b2      = (const float*)d_in[12];
    float* out = (float*)d_out;

    float *p_qkv, *p_aq, *p_ln, *p_lnr, *p_h, *p_gate, *p_wqkvT, *p_w1T, *p_w2T;
    cudaGetSymbolAddress((void**)&p_qkv,   g_qkv);
    cudaGetSymbolAddress((void**)&p_aq,    g_aq);
    cudaGetSymbolAddress((void**)&p_ln,    g_ln);
    cudaGetSymbolAddress((void**)&p_lnr,   g_lnr);
    cudaGetSymbolAddress((void**)&p_h,     g_h);
    cudaGetSymbolAddress((void**)&p_gate,  g_gate);
    cudaGetSymbolAddress((void**)&p_wqkvT, g_wqkvT);
    cudaGetSymbolAddress((void**)&p_w1T,   g_w1T);
    cudaGetSymbolAddress((void**)&p_w2T,   g_w2T);

    const int GSMEM = STAGE_F * 2 * 4;   // 73728 bytes
    cudaFuncSetAttribute(gemm_mma_kernel, cudaFuncAttributeMaxDynamicSharedMemorySize, GSMEM);

    // 0) weight transposes (+tf32 round) and activation round
    transpose_round_kernel<<<dim3(N_QKV / 32, DD / 32), dim3(32, 8)>>>(Wqkv, p_wqkvT, DD, N_QKV);
    transpose_round_kernel<<<dim3(FF_IN / 32, DD / 32), dim3(32, 8)>>>(W1, p_w1T, DD, FF_IN);
    transpose_round_kernel<<<dim3(DD / 32, FF_HID / 32), dim3(32, 8)>>>(W2, p_w2T, FF_HID, DD);
    round_copy_kernel<<<ROWS * DD / 4 / 256, 256>>>(q, p_aq);

    // 1) QKV projection: [8192,1024] @ [1024,3072] + bqkv
    gemm_mma_kernel<<<dim3(N_QKV / GBN, ROWS / GBM), 256, GSMEM>>>(
        p_aq, p_wqkvT, bqkv, nullptr, p_qkv, N_QKV, DD);

    // 2) l2norm + scale + RoPE
    normrope_kernel<<<(BB * SS * HH) / 8, 256>>>(q_scale, k_scale);

    // 3) attention
    attn_kernel<<<dim3(BB * HH, SS / 128), 128>>>();

    // 4) LayerNorm
    ln_kernel<<<ROWS, 256>>>(ln_g, ln_b);

    // 5) FF1: [8192,1024] @ [1024,4096] + b1
    gemm_mma_kernel<<<dim3(FF_IN / GBN, ROWS / GBM), 256, GSMEM>>>(
        p_lnr, p_w1T, b1, nullptr, p_h, FF_IN, DD);

    // 6) SwiGLU
    swiglu_kernel<<<(ROWS * FF_HID / 4) / 256, 256>>>();

    // 7) FF2 + bias + residual(ln)
    gemm_mma_kernel<<<dim3(DD / GBN, ROWS / GBM), 256, GSMEM>>>(
        p_gate, p_w2T, b2, p_ln, out, DD, FF_HID);
}

// round 9
// speedup vs baseline: 4.6629x; 2.7561x over previous
#include <cuda_runtime.h>
#include <math.h>
#include <stdint.h>

// Problem constants
#define BB 4
#define SS 2048
#define HH 16
#define DH 64
#define DD 1024            // H*DH
#define ROWS (BB*SS)       // 8192
#define N_QKV (3*DD)       // 3072
#define FF_IN 4096
#define FF_HID 2048

// Scratch (device globals; no allocation)
__device__ float g_qkv [(size_t)ROWS * N_QKV];   // [B*S, 3072]
__device__ float g_aq  [(size_t)ROWS * DD];      // tf32-rounded q
__device__ float g_q   [(size_t)ROWS * DD];      // [B*H, S, 64] tf32, pre-scaled 0.125
__device__ float g_k   [(size_t)ROWS * DD];      // [B*H, S, 64] tf32
__device__ float g_v   [(size_t)ROWS * DD];      // [B*H, S, 64] raw
__device__ float g_vT  [(size_t)ROWS * DD];      // [B*H, 64, S] tf32
__device__ float g_attn[(size_t)ROWS * DD];      // [B*S, 1024]
__device__ float g_ln  [(size_t)ROWS * DD];      // LN out (fp32, residual)
__device__ float g_lnr [(size_t)ROWS * DD];      // LN out tf32-rounded (GEMM A)
__device__ float g_h   [(size_t)ROWS * FF_IN];   // [B*S, 4096]
__device__ float g_gate[(size_t)ROWS * FF_HID];  // [B*S, 2048] tf32-rounded
__device__ float g_wqkvT[(size_t)N_QKV * DD];    // [3072, 1024]
__device__ float g_w1T  [(size_t)FF_IN * DD];    // [4096, 1024]
__device__ float g_w2T  [(size_t)DD * FF_HID];   // [1024, 2048]

// ---------------------------------------------------------------------------
// helpers
// ---------------------------------------------------------------------------
__device__ __forceinline__ float tf32r(float x) {
    float o; asm("cvt.rna.tf32.f32 %0, %1;" : "=f"(o) : "f"(x)); return o;
}
__device__ __forceinline__ uint32_t smem_u32(const void* p) {
    uint32_t a;
    asm("{ .reg .u64 t; cvta.to.shared.u64 t, %1; cvt.u32.u64 %0, t; }" : "=r"(a) : "l"(p));
    return a;
}
__device__ __forceinline__ void cpasync16(uint32_t dst, const void* src) {
    asm volatile("cp.async.cg.shared.global [%0], [%1], 16;" :: "r"(dst), "l"(src) : "memory");
}
__device__ __forceinline__ void cp_commit() {
    asm volatile("cp.async.commit_group;" ::: "memory");
}
__device__ __forceinline__ void cp_wait1() {
    asm volatile("cp.async.wait_group 1;" ::: "memory");
}
__device__ __forceinline__ void cp_wait0() {
    asm volatile("cp.async.wait_group 0;" ::: "memory");
}
__device__ __forceinline__ void mma_tf32(float* c, const uint32_t* a, const uint32_t* b) {
    asm volatile(
        "mma.sync.aligned.m16n8k8.row.col.f32.tf32.tf32.f32 "
        "{%0,%1,%2,%3}, {%4,%5,%6,%7}, {%8,%9}, {%0,%1,%2,%3};"
        : "+f"(c[0]), "+f"(c[1]), "+f"(c[2]), "+f"(c[3])
        : "r"(a[0]), "r"(a[1]), "r"(a[2]), "r"(a[3]), "r"(b[0]), "r"(b[1]));
}

// ---------------------------------------------------------------------------
// tf32 mma.sync GEMM: C[M,N] = A[M,K] @ Bt[N,K]^T + bias (+ res)
// ---------------------------------------------------------------------------
#define GBM 128
#define GBN 128
#define GBK 32
#define APAD 36
#define STAGE_F (2 * 128 * APAD)   // floats per stage (A+B)

__global__ __launch_bounds__(256) void gemm_mma_kernel(
    const float* __restrict__ A, const float* __restrict__ Bt,
    const float* __restrict__ bias, const float* __restrict__ res,
    float* __restrict__ C, int N, int K)
{
    extern __shared__ float sm[];
    const int tid = threadIdx.x;
    const int wid = tid >> 5, lane = tid & 31;
    const int g = lane >> 2, tg = lane & 3;
    const int warp_m = wid & 3, warp_n = wid >> 2;
    const int m0 = blockIdx.y * GBM, n0 = blockIdx.x * GBN;
    const uint32_t smbase = smem_u32(sm);

    float acc[2][8][4] = {};

    const int NIT = K >> 5;

    auto load_stage = [&](int it, int s) {
        const int k0 = it * GBK;
        const uint32_t aB = smbase + (uint32_t)s * STAGE_F * 4;
        const uint32_t bB = aB + 128 * APAD * 4;
#pragma unroll
        for (int i = 0; i < 4; i++) {
            const int idx = tid + 256 * i;
            const int row = idx >> 3, c4 = (idx & 7) * 4;
            cpasync16(aB + (uint32_t)(row * APAD + c4) * 4,
                      A  + (size_t)(m0 + row) * K + k0 + c4);
            cpasync16(bB + (uint32_t)(row * APAD + c4) * 4,
                      Bt + (size_t)(n0 + row) * K + k0 + c4);
        }
        cp_commit();
    };

    load_stage(0, 0);

    for (int it = 0; it < NIT; it++) {
        const int s = it & 1;
        if (it + 1 < NIT) load_stage(it + 1, s ^ 1);
        if (it + 1 < NIT) cp_wait1(); else cp_wait0();
        __syncthreads();

        const uint32_t* Asm = (const uint32_t*)(sm + s * STAGE_F);
        const uint32_t* Bsm = Asm + 128 * APAD;

#pragma unroll
        for (int kt = 0; kt < 4; kt++) {
            const int k = kt * 8;
            uint32_t a[2][4], b[8][2];
#pragma unroll
            for (int mi = 0; mi < 2; mi++) {
                const uint32_t* ap = Asm + (warp_m * 32 + mi * 16 + g) * APAD + k + tg;
                a[mi][0] = ap[0];
                a[mi][1] = ap[8 * APAD];
                a[mi][2] = ap[4];
                a[mi][3] = ap[8 * APAD + 4];
            }
#pragma unroll
            for (int ni = 0; ni < 8; ni++) {
                const uint32_t* bp = Bsm + (warp_n * 64 + ni * 8 + g) * APAD + k + tg;
                b[ni][0] = bp[0];
                b[ni][1] = bp[4];
            }
#pragma unroll
            for (int mi = 0; mi < 2; mi++)
#pragma unroll
                for (int ni = 0; ni < 8; ni++)
                    mma_tf32(acc[mi][ni], a[mi], b[ni]);
        }
        __syncthreads();
    }

#pragma unroll
    for (int mi = 0; mi < 2; mi++) {
        const int row0 = m0 + warp_m * 32 + mi * 16 + g;
#pragma unroll
        for (int ni = 0; ni < 8; ni++) {
            const int col = n0 + warp_n * 64 + ni * 8 + tg * 2;
            const float2 bv = *(const float2*)(bias + col);
            float2 o0, o1;
            o0.x = acc[mi][ni][0] + bv.x;
            o0.y = acc[mi][ni][1] + bv.y;
            o1.x = acc[mi][ni][2] + bv.x;
            o1.y = acc[mi][ni][3] + bv.y;
            if (res) {
                const float2 r0 = *(const float2*)(res + (size_t)row0 * N + col);
                const float2 r1 = *(const float2*)(res + (size_t)(row0 + 8) * N + col);
                o0.x += r0.x; o0.y += r0.y; o1.x += r1.x; o1.y += r1.y;
            }
            *(float2*)(C + (size_t)row0 * N + col) = o0;
            *(float2*)(C + (size_t)(row0 + 8) * N + col) = o1;
        }
    }
}

// ---------------------------------------------------------------------------
// Transpose + tf32-round: out[c*R + r] = rnd(in[r*Cc + c])
// ---------------------------------------------------------------------------
__global__ __launch_bounds__(256) void transpose_round_kernel(
    const float* __restrict__ in, float* __restrict__ out, int R, int Cc)
{
    __shared__ float t[32][33];
    const int bx = blockIdx.x, by = blockIdx.y;
    const int tx = threadIdx.x, ty = threadIdx.y;
#pragma unroll
    for (int i = 0; i < 32; i += 8)
        t[ty + i][tx] = in[(size_t)(by * 32 + ty + i) * Cc + bx * 32 + tx];
    __syncthreads();
#pragma unroll
    for (int i = 0; i < 32; i += 8)
        out[(size_t)(bx * 32 + ty + i) * R + by * 32 + tx] = tf32r(t[tx][ty + i]);
}

// Batched V transpose per head: g_v [bh][s][d] -> g_vT [bh][d][s], tf32-rounded
__global__ __launch_bounds__(256) void transpose_v_kernel()
{
    __shared__ float t[32][33];
    const int bh = blockIdx.z;
    const float* in = g_v + (size_t)bh * SS * DH;
    float* outp = g_vT + (size_t)bh * DH * SS;
    const int s0 = blockIdx.x * 32, d0 = blockIdx.y * 32;
    const int tx = threadIdx.x, ty = threadIdx.y;
#pragma unroll
    for (int i = 0; i < 32; i += 8)
        t[ty + i][tx] = in[(size_t)(s0 + ty + i) * DH + d0 + tx];
    __syncthreads();
#pragma unroll
    for (int i = 0; i < 32; i += 8)
        outp[(size_t)(d0 + ty + i) * SS + s0 + tx] = tf32r(t[tx][ty + i]);
}

__global__ __launch_bounds__(256) void round_copy_kernel(
    const float* __restrict__ in, float* __restrict__ out)
{
    const int i = blockIdx.x * 256 + threadIdx.x;
    float4 v = ((const float4*)in)[i];
    v.x = tf32r(v.x); v.y = tf32r(v.y); v.z = tf32r(v.z); v.w = tf32r(v.w);
    ((float4*)out)[i] = v;
}

// ---------------------------------------------------------------------------
// l2norm + scale + xpos-RoPE, scatter q/k/v to [B*H, S, 64]
// q,k written tf32-rounded; q pre-scaled by 0.125 (softmax scale)
// ---------------------------------------------------------------------------
__global__ __launch_bounds__(256) void normrope_kernel(
    const float* __restrict__ q_scale, const float* __restrict__ k_scale)
{
    const int w    = blockIdx.x * 8 + (threadIdx.x >> 5);
    const int lane = threadIdx.x & 31;

    const int h    = w & 15;
    const int spos = (w >> 4) & (SS - 1);
    const int b    = w >> 15;
    const int bs   = (b * SS + spos);

    const float* base = g_qkv + (size_t)bs * N_QKV + h * 192;

    float q0 = base[lane],       q1 = base[lane + 32];
    float k0 = base[64 + lane],  k1 = base[96 + lane];
    float v0 = base[128 + lane], v1 = base[160 + lane];

    float sq = q0 * q0 + q1 * q1;
    float sk = k0 * k0 + k1 * k1;
#pragma unroll
    for (int o = 16; o > 0; o >>= 1) {
        sq += __shfl_xor_sync(0xffffffffu, sq, o);
        sk += __shfl_xor_sync(0xffffffffu, sk, o);
    }
    const float invq = 1.0f / fmaxf(sqrtf(sq), 1e-12f);
    const float invk = 1.0f / fmaxf(sqrtf(sk), 1e-12f);

    q0 = q0 * invq * q_scale[lane];
    q1 = q1 * invq * q_scale[lane + 32];
    k0 = k0 * invk * k_scale[lane];
    k1 = k1 * invk * k_scale[lane + 32];

    const float inv_freq = expf(-((2.0f * lane) / 64.0f) * 9.210340371976184f);
    const float f = (float)spos * inv_freq;
    float sn, cs;
    sincosf(f, &sn, &cs);
    const float power = ((float)spos - 1024.0f) * (1.0f / 512.0f);
    const float bse   = (2.0f * lane + 25.6f) * (1.0f / 89.6f);
    const float sc    = powf(bse, power);
    const float sci   = 1.0f / sc;

    const float q0r = (q0 * cs - q1 * sn) * sc;
    const float q1r = (q1 * cs + q0 * sn) * sc;
    const float k0r = (k0 * cs - k1 * sn) * sci;
    const float k1r = (k1 * cs + k0 * sn) * sci;

    const int bh = b * HH + h;
    const size_t o = ((size_t)bh * SS + spos) * DH;
    g_q[o + lane]      = tf32r(q0r * 0.125f);
    g_q[o + lane + 32] = tf32r(q1r * 0.125f);
    g_k[o + lane]      = tf32r(k0r);
    g_k[o + lane + 32] = tf32r(k1r);
    g_v[o + lane] = v0;   g_v[o + lane + 32] = v1;
}

// ---------------------------------------------------------------------------
// Flash attention via mma.sync tf32.
// CTA: 128 q-rows, 4 warps x 32 rows. K/V tiles of 64 keys, double-buffered.
// Q[128x64] smem; K tile [key][d]; V^T tile [d][key]. Online softmax in frags.
// ---------------------------------------------------------------------------
#define ATT_PAD 68
#define ATT_QF   (128 * ATT_PAD)           // Q floats
#define ATT_STF  (2 * 64 * ATT_PAD)        // per-stage floats (K + V^T)

__global__ __launch_bounds__(128) void attn_mma_kernel()
{
    extern __shared__ float sm[];
    float* Qs = sm;
    float* Stg = sm + ATT_QF;

    const int bh = blockIdx.x;
    const int q0 = blockIdx.y * 128;
    const int tid = threadIdx.x, wid = tid >> 5, lane = tid & 31;
    const int g = lane >> 2, tg = lane & 3;
    const uint32_t smbase = smem_u32(sm);

    const float* Q  = g_q + ((size_t)bh * SS + q0) * DH;
    const float* K  = g_k + (size_t)bh * SS * DH;
    const float* Vt = g_vT + (size_t)bh * DH * SS;

    // load Q tile into smem (pad 68)
    for (int i = tid; i < 128 * 16; i += 128) {
        const int r = i >> 4, c4 = (i & 15) * 4;
        *(float4*)(&Qs[r * ATT_PAD + c4]) = *(const float4*)(Q + r * DH + c4);
    }

    // K tile: 64 rows x 64 floats = 1024 x 16B; V^T tile same => 8 iters x 128 thr
    auto load_kv = [&](int t, int s) {
        const uint32_t kB = smbase + (ATT_QF + s * ATT_STF) * 4;
        const uint32_t vB = kB + 64 * ATT_PAD * 4;
        const float* Kg = K + (size_t)t * 64 * DH;
#pragma unroll
        for (int i = 0; i < 8; i++) {
            const int idx = tid + 128 * i;
            const int r = idx >> 4, c4 = (idx & 15) * 4;
            cpasync16(kB + (uint32_t)(r * ATT_PAD + c4) * 4, Kg + r * DH + c4);
            cpasync16(vB + (uint32_t)(r * ATT_PAD + c4) * 4, Vt + (size_t)r * SS + t * 64 + c4);
        }
        cp_commit();
    };

    load_kv(0, 0);

    float acc[2][8][4] = {};
    float mrow[4] = {-1e30f, -1e30f, -1e30f, -1e30f};
    float lrow[4] = {};

    const int NT = SS / 64;   // 32 key tiles
    for (int t = 0; t < NT; t++) {
        const int s = t & 1;
        if (t + 1 < NT) load_kv(t + 1, s ^ 1);
        if (t + 1 < NT) cp_wait1(); else cp_wait0();
        __syncthreads();

        const uint32_t* Ks = (const uint32_t*)(Stg + s * ATT_STF);
        const uint32_t* Vs = Ks + 64 * ATT_PAD;

        // --- S = Q @ K^T (32x64 per warp) ---
        float sc[2][8][4] = {};
#pragma unroll
        for (int kt = 0; kt < 8; kt++) {
            uint32_t aq[2][4], bk[8][2];
#pragma unroll
            for (int mi = 0; mi < 2; mi++) {
                const uint32_t* ap = (const uint32_t*)Qs + (wid * 32 + mi * 16 + g) * ATT_PAD + kt * 8 + tg;
                aq[mi][0] = ap[0];
                aq[mi][1] = ap[8 * ATT_PAD];
                aq[mi][2] = ap[4];
                aq[mi][3] = ap[8 * ATT_PAD + 4];
            }
#pragma unroll
            for (int ni = 0; ni < 8; ni++) {
                const uint32_t* bp = Ks + (ni * 8 + g) * ATT_PAD + kt * 8 + tg;
                bk[ni][0] = bp[0];
                bk[ni][1] = bp[4];
            }
#pragma unroll
            for (int mi = 0; mi < 2; mi++)
#pragma unroll
                for (int ni = 0; ni < 8; ni++)
                    mma_tf32(sc[mi][ni], aq[mi], bk[ni]);
        }

        // --- online softmax (q pre-scaled by 0.125) ---
#pragma unroll
        for (int mi = 0; mi < 2; mi++) {
#pragma unroll
            for (int hf = 0; hf < 2; hf++) {
                const int r = mi * 2 + hf;
                float mx = -1e30f;
#pragma unroll
                for (int ni = 0; ni < 8; ni++)
                    mx = fmaxf(mx, fmaxf(sc[mi][ni][hf * 2], sc[mi][ni][hf * 2 + 1]));
                mx = fmaxf(mx, __shfl_xor_sync(0xffffffffu, mx, 1));
                mx = fmaxf(mx, __shfl_xor_sync(0xffffffffu, mx, 2));
                const float newm = fmaxf(mrow[r], mx);
                const float corr = __expf(mrow[r] - newm);
                mrow[r] = newm;
                float sum = 0.0f;
#pragma unroll
                for (int ni = 0; ni < 8; ni++) {
                    const float p0 = __expf(sc[mi][ni][hf * 2]     - newm);
                    const float p1 = __expf(sc[mi][ni][hf * 2 + 1] - newm);
                    sum += p0 + p1;
                    sc[mi][ni][hf * 2]     = p0;
                    sc[mi][ni][hf * 2 + 1] = p1;
                }
                sum += __shfl_xor_sync(0xffffffffu, sum, 1);
                sum += __shfl_xor_sync(0xffffffffu, sum, 2);
                lrow[r] = lrow[r] * corr + sum;
#pragma unroll
                for (int nd = 0; nd < 8; nd++) {
                    acc[mi][nd][hf * 2]     *= corr;
                    acc[mi][nd][hf * 2 + 1] *= corr;
                }
            }
        }

        // --- O += P @ V : convert P frags (C-layout -> A-layout via shfl) ---
        const int src0 = g * 4 + (tg >> 1);
        const int src1 = src0 + 2;
        const bool odd = tg & 1;
#pragma unroll
        for (int kt = 0; kt < 8; kt++) {
            uint32_t ap[2][4];
#pragma unroll
            for (int mi = 0; mi < 2; mi++) {
                const float c0 = sc[mi][kt][0], c1 = sc[mi][kt][1];
                const float c2 = sc[mi][kt][2], c3 = sc[mi][kt][3];
                const float v00 = __shfl_sync(0xffffffffu, c0, src0);
                const float v01 = __shfl_sync(0xffffffffu, c1, src0);
                const float v10 = __shfl_sync(0xffffffffu, c0, src1);
                const float v11 = __shfl_sync(0xffffffffu, c1, src1);
                const float v20 = __shfl_sync(0xffffffffu, c2, src0);
                const float v21 = __shfl_sync(0xffffffffu, c3, src0);
                const float v30 = __shfl_sync(0xffffffffu, c2, src1);
                const float v31 = __shfl_sync(0xffffffffu, c3, src1);
                ap[mi][0] = __float_as_uint(tf32r(odd ? v01 : v00));
                ap[mi][1] = __float_as_uint(tf32r(odd ? v21 : v20));
                ap[mi][2] = __float_as_uint(tf32r(odd ? v11 : v10));
                ap[mi][3] = __float_as_uint(tf32r(odd ? v31 : v30));
            }
            uint32_t bv[8][2];
#pragma unroll
            for (int nd = 0; nd < 8; nd++) {
                const uint32_t* bp = Vs + (nd * 8 + g) * ATT_PAD + kt * 8 + tg;
                bv[nd][0] = bp[0];
                bv[nd][1] = bp[4];
            }
#pragma unroll
            for (int mi = 0; mi < 2; mi++)
#pragma unroll
                for (int nd = 0; nd < 8; nd++)
                    mma_tf32(acc[mi][nd], ap[mi], bv[nd]);
        }
        __syncthreads();
    }

    // --- write O (normalize by l) ---
    const int b = bh >> 4, h = bh & 15;
#pragma unroll
    for (int mi = 0; mi < 2; mi++) {
        const int row0 = q0 + wid * 32 + mi * 16 + g;
        const float inv0 = 1.0f / lrow[mi * 2 + 0];
        const float inv1 = 1.0f / lrow[mi * 2 + 1];
#pragma unroll
        for (int nd = 0; nd < 8; nd++) {
            const int col = h * 64 + nd * 8 + tg * 2;
            float2 o0, o1;
            o0.x = acc[mi][nd][0] * inv0; o0.y = acc[mi][nd][1] * inv0;
            o1.x = acc[mi][nd][2] * inv1; o1.y = acc[mi][nd][3] * inv1;
            *(float2*)(g_attn + ((size_t)(b * SS + row0)) * DD + col) = o0;
            *(float2*)(g_attn + ((size_t)(b * SS + row0 + 8)) * DD + col) = o1;
        }
    }
}

// ---------------------------------------------------------------------------
// LayerNorm; writes fp32 g_ln (residual) and tf32-rounded g_lnr (GEMM A)
// ---------------------------------------------------------------------------
__global__ __launch_bounds__(256) void ln_kernel(
    const float* __restrict__ gw, const float* __restrict__ bw)
{
    __shared__ float red[64];
    const int r = blockIdx.x;
    const int t = threadIdx.x;

    const float4 x = ((const float4*)(g_attn + (size_t)r * DD))[t];
    float s  = x.x + x.y + x.z + x.w;
    float ss = x.x*x.x + x.y*x.y + x.z*x.z + x.w*x.w;
#pragma unroll
    for (int o = 16; o > 0; o >>= 1) {
        s  += __shfl_xor_sync(0xffffffffu, s,  o);
        ss += __shfl_xor_sync(0xffffffffu, ss, o);
    }
    if ((t & 31) == 0) { red[t >> 5] = s; red[32 + (t >> 5)] = ss; }
    __syncthreads();
    if (t == 0) {
        float S = 0, SSum = 0;
#pragma unroll
        for (int i = 0; i < 8; i++) { S += red[i]; SSum += red[32 + i]; }
        red[0] = S; red[32] = SSum;
    }
    __syncthreads();
    const float mu  = red[0]  * (1.0f / DD);
    const float var = red[32] * (1.0f / DD) - mu * mu;
    const float inv = rsqrtf(var + 1e-5f);

    const int c = t * 4;
    float4 o;
    o.x = (x.x - mu) * inv * gw[c + 0] + bw[c + 0];
    o.y = (x.y - mu) * inv * gw[c + 1] + bw[c + 1];
    o.z = (x.z - mu) * inv * gw[c + 2] + bw[c + 2];
    o.w = (x.w - mu) * inv * gw[c + 3] + bw[c + 3];
    ((float4*)(g_ln + (size_t)r * DD))[t] = o;
    float4 orr;
    orr.x = tf32r(o.x); orr.y = tf32r(o.y); orr.z = tf32r(o.z); orr.w = tf32r(o.w);
    ((float4*)(g_lnr + (size_t)r * DD))[t] = orr;
}

// ---------------------------------------------------------------------------
// SwiGLU (tf32-rounded output for FF2 A operand)
// ---------------------------------------------------------------------------
__global__ __launch_bounds__(256) void swiglu_kernel()
{
    const int idx4 = blockIdx.x * 256 + threadIdx.x;
    const int r    = idx4 >> 9;
    const int c4   = idx4 & 511;
    const float4 xv = ((const float4*)(g_h + (size_t)r * FF_IN))[c4];
    const float4 gv = ((const float4*)(g_h + (size_t)r * FF_IN + FF_HID))[c4];
    float4 o;
    o.x = tf32r(xv.x * gv.x / (1.0f + __expf(-gv.x)));
    o.y = tf32r(xv.y * gv.y / (1.0f + __expf(-gv.y)));
    o.z = tf32r(xv.z * gv.z / (1.0f + __expf(-gv.z)));
    o.w = tf32r(xv.w * gv.w / (1.0f + __expf(-gv.w)));
    ((float4*)(g_gate + (size_t)r * FF_HID))[c4] = o;
}

// ---------------------------------------------------------------------------
extern "C" void kernel_launch(void* const* d_in, const int* in_sizes, int n_in,
                              void* d_out, int out_size)
{
    const float* q       = (const float*)d_in[0];
    const float* Wqkv    = (const float*)d_in[3];
    const float* bqkv    = (const float*)d_in[4];
    const float* q_scale = (const float*)d_in[5];
    const float* k_scale = (const float*)d_in[6];
    const float* ln_g    = (const float*)d_in[7];
    const float* ln_b    = (const float*)d_in[8];
    const float* W1      = (const float*)d_in[9];
    const float* b1      = (const float*)d_in[10];
    const float* W2      = (const float*)d_in[11];
    const float* b2      = (const float*)d_in[12];
    float* out = (float*)d_out;

    float *p_qkv, *p_aq, *p_ln, *p_lnr, *p_h, *p_gate, *p_wqkvT, *p_w1T, *p_w2T;
    cudaGetSymbolAddress((void**)&p_qkv,   g_qkv);
    cudaGetSymbolAddress((void**)&p_aq,    g_aq);
    cudaGetSymbolAddress((void**)&p_ln,    g_ln);
    cudaGetSymbolAddress((void**)&p_lnr,   g_lnr);
    cudaGetSymbolAddress((void**)&p_h,     g_h);
    cudaGetSymbolAddress((void**)&p_gate,  g_gate);
    cudaGetSymbolAddress((void**)&p_wqkvT, g_wqkvT);
    cudaGetSymbolAddress((void**)&p_w1T,   g_w1T);
    cudaGetSymbolAddress((void**)&p_w2T,   g_w2T);

    const int GSMEM = STAGE_F * 2 * 4;                    // 73728 bytes
    const int ASMEM = (ATT_QF + 2 * ATT_STF) * 4;         // 104448 bytes
    cudaFuncSetAttribute(gemm_mma_kernel, cudaFuncAttributeMaxDynamicSharedMemorySize, GSMEM);
    cudaFuncSetAttribute(attn_mma_kernel, cudaFuncAttributeMaxDynamicSharedMemorySize, ASMEM);

    // 0) weight transposes (+tf32 round) and activation round
    transpose_round_kernel<<<dim3(N_QKV / 32, DD / 32), dim3(32, 8)>>>(Wqkv, p_wqkvT, DD, N_QKV);
    transpose_round_kernel<<<dim3(FF_IN / 32, DD / 32), dim3(32, 8)>>>(W1, p_w1T, DD, FF_IN);
    transpose_round_kernel<<<dim3(DD / 32, FF_HID / 32), dim3(32, 8)>>>(W2, p_w2T, FF_HID, DD);
    round_copy_kernel<<<ROWS * DD / 4 / 256, 256>>>(q, p_aq);

    // 1) QKV projection
    gemm_mma_kernel<<<dim3(N_QKV / GBN, ROWS / GBM), 256, GSMEM>>>(
        p_aq, p_wqkvT, bqkv, nullptr, p_qkv, N_QKV, DD);

    // 2) l2norm + scale + RoPE (q pre-scaled by 0.125, tf32-rounded)
    normrope_kernel<<<(BB * SS * HH) / 8, 256>>>(q_scale, k_scale);

    // 2b) V transpose per head (tf32-rounded)
    transpose_v_kernel<<<dim3(SS / 32, DH / 32, BB * HH), dim3(32, 8)>>>();

    // 3) attention (tensor cores)
    attn_mma_kernel<<<dim3(BB * HH, SS / 128), 128, ASMEM>>>();

    // 4) LayerNorm
    ln_kernel<<<ROWS, 256>>>(ln_g, ln_b);

    // 5) FF1
    gemm_mma_kernel<<<dim3(FF_IN / GBN, ROWS / GBM), 256, GSMEM>>>(
        p_lnr, p_w1T, b1, nullptr, p_h, FF_IN, DD);

    // 6) SwiGLU
    swiglu_kernel<<<(ROWS * FF_HID / 4) / 256, 256>>>();

    // 7) FF2 + bias + residual(ln)
    gemm_mma_kernel<<<dim3(DD / GBN, ROWS / GBM), 256, GSMEM>>>(
        p_gate, p_w2T, b2, p_ln, out, DD, FF_HID);
}